// round 8
// baseline (speedup 1.0000x reference)
#include <cuda_runtime.h>
#include <cuda_fp16.h>

// Swin window attention, fully fused: one CTA per 8x8 window, 4 CTAs/SM.
// Q never touches smem; max-free half2 softmax via ex2.approx.f16x2 (log2-domain);
// rel-pos bias injected as MMA C-operand (LDG.128 batched); residual x prefetched.

#define NWIN   8192
#define TPB    256
#define LOG2E  1.4426950408889634f

// smem layout (bytes)
#define OFF_XN   0        // half [64][72]   9216  (LN output Z; later attn-out AO)
#define OFF_KV   9216     // half [64][136] 17408  (K cols 0-63, V cols 64-127)
#define SMEM_BYTES 26624

// pre-baked tables (prep kernel fills these)
__device__ unsigned g_qkvfrag[3072 * 2];   // [ntile0..23][kt0..3][lane][2]  (LN+scale folded)
__device__ unsigned g_projfrag[1024 * 2];  // [ntile0..7][kt][lane][2]
__device__ unsigned g_qkvbh[96];           // half2 qkv bias per col-pair (scale folded)
__device__ unsigned g_biasfh[4096 * 2];    // [warp][mt][lane][j] uint2: bias*log2e frags

__device__ __forceinline__ unsigned packh2f(float lo, float hi) {
    __half2 h = __floats2half2_rn(lo, hi);
    return *reinterpret_cast<unsigned*>(&h);
}

__global__ void prep_kernel(const float* __restrict__ qw, const float* __restrict__ pw,
                            const float* __restrict__ nw, const float* __restrict__ nb,
                            const float* __restrict__ rpb) {
    int idx = blockIdx.x * blockDim.x + threadIdx.x;   // 32 blocks * 256 = 8192

    if (idx < 3072) {  // qkv weight fragments (norm_w + q-scale*log2e folded)
        int lane = idx & 31, kt = (idx >> 5) & 3, ntile = idx >> 7;
        int n  = ntile * 8 + (lane >> 2);
        int k0 = kt * 16 + (lane & 3) * 2;
        float sc = (n < 64) ? 0.25f * LOG2E : 1.0f;
        const float* wr = qw + n * 64;
        g_qkvfrag[idx * 2 + 0] = packh2f(wr[k0] * nw[k0] * sc,         wr[k0 + 1] * nw[k0 + 1] * sc);
        g_qkvfrag[idx * 2 + 1] = packh2f(wr[k0 + 8] * nw[k0 + 8] * sc, wr[k0 + 9] * nw[k0 + 9] * sc);
    }
    if (idx < 1024) {  // proj weight fragments
        int lane = idx & 31, kt = (idx >> 5) & 3, ntile = idx >> 7;
        int n  = ntile * 8 + (lane >> 2);
        int k0 = kt * 16 + (lane & 3) * 2;
        const float* wr = pw + n * 64;
        g_projfrag[idx * 2 + 0] = packh2f(wr[k0],     wr[k0 + 1]);
        g_projfrag[idx * 2 + 1] = packh2f(wr[k0 + 8], wr[k0 + 9]);
    }
    if (idx < 96) {    // folded LN-bias through qkv (per output col pair), scale folded
        float b0 = 0.f, b1 = 0.f;
        int c = idx * 2;
        for (int k = 0; k < 64; k++) {
            b0 += nb[k] * qw[c * 64 + k];
            b1 += nb[k] * qw[(c + 1) * 64 + k];
        }
        float sc = (c < 64) ? 0.25f * LOG2E : 1.0f;
        g_qkvbh[idx] = packh2f(b0 * sc, b1 * sc);
    }
    if (idx < 4096) {  // rel-pos bias fragments, layout [warp][mt][lane][j] (uint2 each)
        int j    = idx & 7;
        int lane = (idx >> 3) & 31;
        int mt   = (idx >> 8) & 1;
        int warp = idx >> 9;
        int h  = warp >> 1;
        int m0 = (warp & 1) * 32;
        int g  = lane >> 2, tig = lane & 3;
        int rr = m0 + mt * 16 + g;
        int cc = j * 8 + tig * 2;
        auto bias = [&](int r, int c) {
            int dy = (r >> 3) - (c >> 3);
            int dx = (r & 7) - (c & 7);
            return rpb[((dy + 7) * 15 + (dx + 7)) * 4 + h] * LOG2E;
        };
        g_biasfh[idx * 2 + 0] = packh2f(bias(rr, cc),     bias(rr, cc + 1));
        g_biasfh[idx * 2 + 1] = packh2f(bias(rr + 8, cc), bias(rr + 8, cc + 1));
    }
}

__device__ __forceinline__ unsigned saddr(const void* p) {
    return (unsigned)__cvta_generic_to_shared(p);
}
__device__ __forceinline__ void ldsm_x4(unsigned a, unsigned& r0, unsigned& r1, unsigned& r2, unsigned& r3) {
    asm volatile("ldmatrix.sync.aligned.m8n8.x4.shared.b16 {%0,%1,%2,%3}, [%4];"
                 : "=r"(r0), "=r"(r1), "=r"(r2), "=r"(r3) : "r"(a));
}
__device__ __forceinline__ void ldsm_x4t(unsigned a, unsigned& r0, unsigned& r1, unsigned& r2, unsigned& r3) {
    asm volatile("ldmatrix.sync.aligned.m8n8.x4.trans.shared.b16 {%0,%1,%2,%3}, [%4];"
                 : "=r"(r0), "=r"(r1), "=r"(r2), "=r"(r3) : "r"(a));
}
__device__ __forceinline__ void mmah(uint2& c, unsigned a0, unsigned a1, unsigned a2, unsigned a3,
                                     unsigned b0, unsigned b1) {
    asm volatile("mma.sync.aligned.m16n8k16.row.col.f16.f16.f16.f16 "
                 "{%0,%1}, {%2,%3,%4,%5}, {%6,%7}, {%0,%1};"
                 : "+r"(c.x), "+r"(c.y)
                 : "r"(a0), "r"(a1), "r"(a2), "r"(a3), "r"(b0), "r"(b1));
}
__device__ __forceinline__ unsigned hadd2u(unsigned a, unsigned b) {
    __half2 r = __hadd2(*(__half2*)&a, *(__half2*)&b);
    return *(unsigned*)&r;
}
__device__ __forceinline__ unsigned hmul2u(unsigned a, unsigned b) {
    __half2 r = __hmul2(*(__half2*)&a, *(__half2*)&b);
    return *(unsigned*)&r;
}
__device__ __forceinline__ unsigned ex2h2(unsigned a) {
    unsigned r;
    asm("ex2.approx.f16x2 %0, %1;" : "=r"(r) : "r"(a));
    return r;
}
__device__ __forceinline__ unsigned hswap(unsigned a) {      // swap the two halves
    return __byte_perm(a, a, 0x1032);
}
__device__ __forceinline__ float2 h2f2(unsigned u) {
    return __half22float2(*(__half2*)&u);
}
__device__ __forceinline__ float hlo2f(unsigned u) {
    return __half2float(__low2half(*(__half2*)&u));
}

__global__ __launch_bounds__(256, 4)
void ewa_kernel(const float* __restrict__ x,
                const float* __restrict__ ascale,
                float* __restrict__ out) {
    extern __shared__ char smem[];
    __half* XN = (__half*)(smem + OFF_XN);   // [64][72]  Z / AO
    __half* KV = (__half*)(smem + OFF_KV);   // [64][136] K | V

    const int tid  = threadIdx.x;
    const int lane = tid & 31;
    const int warp = tid >> 5;
    const int g    = lane >> 2;
    const int tig  = lane & 3;
    const int l2   = lane & 15;

    const int win = blockIdx.x;
    const int b   = win >> 10;
    const int rem = win & 1023;
    const int wy  = rem >> 5;
    const int wx  = rem & 31;

    const int h  = warp >> 1;          // head (phases 2-3)
    const int m0 = (warp & 1) * 32;

    // ---- Phase 1: direct token-major load + in-register LayerNorm -> XN (fp16 Z) ----
    {
        int t = tid >> 2, q = tid & 3;            // token, channel quarter
        int pix = (wy * 8 + (t >> 3)) * 256 + wx * 8 + (t & 7);
        const float* base = x + (b * 64 + q * 16) * 65536 + pix;
        float v[16];
        #pragma unroll
        for (int i = 0; i < 16; i++) v[i] = base[i * 65536];
        float s = 0.f, ss = 0.f;
        #pragma unroll
        for (int i = 0; i < 16; i++) { s += v[i]; ss += v[i] * v[i]; }
        s  += __shfl_xor_sync(0xffffffffu, s, 1);  ss += __shfl_xor_sync(0xffffffffu, ss, 1);
        s  += __shfl_xor_sync(0xffffffffu, s, 2);  ss += __shfl_xor_sync(0xffffffffu, ss, 2);
        float mu   = s * (1.f / 64.f);
        float var  = ss * (1.f / 64.f) - mu * mu;
        float rstd = rsqrtf(var + 1e-5f);
        unsigned h8[8];
        #pragma unroll
        for (int i = 0; i < 8; i++)
            h8[i] = packh2f((v[2 * i] - mu) * rstd, (v[2 * i + 1] - mu) * rstd);
        uint4* dst = (uint4*)(XN + t * 72 + q * 16);
        dst[0] = make_uint4(h8[0], h8[1], h8[2], h8[3]);
        dst[1] = make_uint4(h8[4], h8[5], h8[6], h8[7]);
    }
    __syncthreads();

    // ---- Phase 2: QKV GEMM. Q for own (head, rows) stays in registers; K/V -> smem ----
    unsigned qa[2][4];   // Q as A-fragments for QK^T, per mt
    {
        uint2 qacc[2][2], kvacc[2][4];
        #pragma unroll
        for (int mt = 0; mt < 2; mt++) {
            qacc[mt][0] = make_uint2(0u, 0u); qacc[mt][1] = make_uint2(0u, 0u);
            #pragma unroll
            for (int j = 0; j < 4; j++) kvacc[mt][j] = make_uint2(0u, 0u);
        }
        #pragma unroll
        for (int kt = 0; kt < 4; kt++) {
            unsigned a[2][4];
            #pragma unroll
            for (int mt = 0; mt < 2; mt++)
                ldsm_x4(saddr(XN + (m0 + mt * 16 + l2) * 72 + kt * 16 + (lane >> 4) * 8),
                        a[mt][0], a[mt][1], a[mt][2], a[mt][3]);
            uint2 qb[2], kvb[4];
            #pragma unroll
            for (int j = 0; j < 2; j++)
                qb[j] = *(const uint2*)(g_qkvfrag + (((h * 2 + j) * 4 + kt) * 32 + lane) * 2);
            #pragma unroll
            for (int j = 0; j < 4; j++)
                kvb[j] = *(const uint2*)(g_qkvfrag + (((8 + h * 4 + j) * 4 + kt) * 32 + lane) * 2);
            #pragma unroll
            for (int mt = 0; mt < 2; mt++) {
                #pragma unroll
                for (int j = 0; j < 2; j++)
                    mmah(qacc[mt][j], a[mt][0], a[mt][1], a[mt][2], a[mt][3], qb[j].x, qb[j].y);
                #pragma unroll
                for (int j = 0; j < 4; j++)
                    mmah(kvacc[mt][j], a[mt][0], a[mt][1], a[mt][2], a[mt][3], kvb[j].x, kvb[j].y);
            }
        }
        // Q: D-frag (+bias) == A-frag for QK^T
        unsigned bq0 = g_qkvbh[h * 8 + tig];
        unsigned bq1 = g_qkvbh[h * 8 + 4 + tig];
        #pragma unroll
        for (int mt = 0; mt < 2; mt++) {
            qa[mt][0] = hadd2u(qacc[mt][0].x, bq0);
            qa[mt][1] = hadd2u(qacc[mt][0].y, bq0);
            qa[mt][2] = hadd2u(qacc[mt][1].x, bq1);
            qa[mt][3] = hadd2u(qacc[mt][1].y, bq1);
        }
        // K/V -> smem (smem col = global col - 64)
        #pragma unroll
        for (int j = 0; j < 4; j++) {
            int col = h * 32 + j * 8 + tig * 2;
            unsigned bh = g_qkvbh[32 + h * 16 + j * 4 + tig];
            #pragma unroll
            for (int mt = 0; mt < 2; mt++) {
                int row = m0 + mt * 16 + g;
                *(unsigned*)(KV + row * 136 + col)       = hadd2u(kvacc[mt][j].x, bh);
                *(unsigned*)(KV + (row + 8) * 136 + col) = hadd2u(kvacc[mt][j].y, bh);
            }
        }
    }
    __syncthreads();

    // ---- Phase 3: attention (log2-domain, max-free half2 softmax, bias as C-init) ----
    {
        unsigned kb[8][2];
        #pragma unroll
        for (int jp = 0; jp < 4; jp++) {        // K fragments via ldmatrix.x4 (2 n-tiles each)
            unsigned r0, r1, r2, r3;
            int j  = (lane >> 4);               // n-tile within pair
            int kh = (lane >> 3) & 1;
            ldsm_x4(saddr(KV + ((jp * 2 + j) * 8 + (lane & 7)) * 136 + h * 16 + kh * 8),
                    r0, r1, r2, r3);
            kb[jp * 2 + 0][0] = r0; kb[jp * 2 + 0][1] = r1;
            kb[jp * 2 + 1][0] = r2; kb[jp * 2 + 1][1] = r3;
        }

        #pragma unroll
        for (int mt = 0; mt < 2; mt++) {
            // bias fragments: one batched read (4x LDG.128)
            const uint4* bfp = (const uint4*)(g_biasfh) + ((warp * 2 + mt) * 32 + lane) * 4;
            uint2 s[8];
            #pragma unroll
            for (int i = 0; i < 4; i++) {
                uint4 bv = bfp[i];
                s[2 * i].x = bv.x;     s[2 * i].y = bv.y;
                s[2 * i + 1].x = bv.z; s[2 * i + 1].y = bv.w;
            }
            #pragma unroll
            for (int j = 0; j < 8; j++)
                mmah(s[j], qa[mt][0], qa[mt][1], qa[mt][2], qa[mt][3], kb[j][0], kb[j][1]);

            // max-free: p = 2^l directly (logits bounded, fp16-safe)
            unsigned sum0 = 0u, sum1 = 0u;
            #pragma unroll
            for (int j = 0; j < 8; j++) {
                s[j].x = ex2h2(s[j].x);
                s[j].y = ex2h2(s[j].y);
                sum0 = hadd2u(sum0, s[j].x);
                sum1 = hadd2u(sum1, s[j].y);
            }

            // AV MMAs issued before the sum shuffle chain (independent)
            uint2 o[2];
            o[0].x = o[0].y = o[1].x = o[1].y = 0u;
            #pragma unroll
            for (int kt = 0; kt < 4; kt++) {
                unsigned v0, v1, v2, v3;
                ldsm_x4t(saddr(KV + (kt * 16 + (lane & 7) + ((lane >> 3) & 1) * 8) * 136
                               + 64 + h * 16 + (lane >> 4) * 8),
                         v0, v1, v2, v3);
                mmah(o[0], s[2 * kt].x, s[2 * kt].y, s[2 * kt + 1].x, s[2 * kt + 1].y, v0, v1);
                mmah(o[1], s[2 * kt].x, s[2 * kt].y, s[2 * kt + 1].x, s[2 * kt + 1].y, v2, v3);
            }

            sum0 = hadd2u(sum0, __shfl_xor_sync(0xffffffffu, sum0, 1));
            sum0 = hadd2u(sum0, __shfl_xor_sync(0xffffffffu, sum0, 2));
            sum0 = hadd2u(sum0, hswap(sum0));
            sum1 = hadd2u(sum1, __shfl_xor_sync(0xffffffffu, sum1, 1));
            sum1 = hadd2u(sum1, __shfl_xor_sync(0xffffffffu, sum1, 2));
            sum1 = hadd2u(sum1, hswap(sum1));

            float f0 = __fdividef(1.f, hlo2f(sum0));
            float f1 = __fdividef(1.f, hlo2f(sum1));
            unsigned i0 = packh2f(f0, f0);
            unsigned i1 = packh2f(f1, f1);
            #pragma unroll
            for (int nt = 0; nt < 2; nt++) {
                int row = m0 + mt * 16 + g;
                int col = h * 16 + nt * 8 + tig * 2;
                *(unsigned*)(XN + row * 72 + col)       = hmul2u(o[nt].x, i0);
                *(unsigned*)(XN + (row + 8) * 72 + col) = hmul2u(o[nt].y, i1);
            }
        }
    }
    __syncthreads();

    // ---- Phase 4: proj GEMM [64,64]x[64,64] + residual + write out (fp16 acc) ----
    {
        const int ntb = (warp >> 1) * 2;      // ntile base (8-col tiles)

        // prefetch residual x (hide L2 latency behind the MMA chain)
        float xv[16];
        int   gix[8];
        #pragma unroll
        for (int mt = 0; mt < 2; mt++)
            #pragma unroll
            for (int nt = 0; nt < 2; nt++)
                #pragma unroll
                for (int hf = 0; hf < 2; hf++) {
                    int k = (mt * 2 + nt) * 2 + hf;
                    int ch  = (ntb + nt) * 8 + tig * 2;
                    int row = m0 + mt * 16 + g + hf * 8;
                    int gi0 = ((b * 64 + ch) * 256 + wy * 8 + (row >> 3)) * 256 + wx * 8 + (row & 7);
                    gix[k] = gi0;
                    xv[k * 2 + 0] = x[gi0];
                    xv[k * 2 + 1] = x[gi0 + 65536];
                }

        uint2 acc[2][2];
        acc[0][0] = make_uint2(0u, 0u); acc[0][1] = make_uint2(0u, 0u);
        acc[1][0] = make_uint2(0u, 0u); acc[1][1] = make_uint2(0u, 0u);
        #pragma unroll
        for (int kt = 0; kt < 4; kt++) {
            unsigned a[2][4];
            #pragma unroll
            for (int mt = 0; mt < 2; mt++)
                ldsm_x4(saddr(XN + (m0 + mt * 16 + l2) * 72 + kt * 16 + (lane >> 4) * 8),
                        a[mt][0], a[mt][1], a[mt][2], a[mt][3]);
            uint2 bf[2];
            #pragma unroll
            for (int nt = 0; nt < 2; nt++)
                bf[nt] = *(const uint2*)(g_projfrag + (((ntb + nt) * 4 + kt) * 32 + lane) * 2);
            #pragma unroll
            for (int mt = 0; mt < 2; mt++)
                #pragma unroll
                for (int nt = 0; nt < 2; nt++)
                    mmah(acc[mt][nt], a[mt][0], a[mt][1], a[mt][2], a[mt][3], bf[nt].x, bf[nt].y);
        }
        float ssc = ascale[0];
        #pragma unroll
        for (int mt = 0; mt < 2; mt++)
            #pragma unroll
            for (int nt = 0; nt < 2; nt++) {
                float2 lo = h2f2(acc[mt][nt].x);   // rows m0+mt*16+g
                float2 hi = h2f2(acc[mt][nt].y);   // rows +8
                #pragma unroll
                for (int hf = 0; hf < 2; hf++) {
                    int k = (mt * 2 + nt) * 2 + hf;
                    float2 v = hf ? hi : lo;
                    out[gix[k]]         = xv[k * 2 + 0] + ssc * v.x;
                    out[gix[k] + 65536] = xv[k * 2 + 1] + ssc * v.y;
                }
            }
    }
}

extern "C" void kernel_launch(void* const* d_in, const int* in_sizes, int n_in,
                              void* d_out, int out_size) {
    const float* x  = (const float*)d_in[0];
    const float* nw = (const float*)d_in[1];
    const float* nb = (const float*)d_in[2];
    const float* qw = (const float*)d_in[3];
    const float* pw = (const float*)d_in[4];
    const float* sc = (const float*)d_in[5];
    const float* rp = (const float*)d_in[6];
    float* out = (float*)d_out;

    cudaFuncSetAttribute(ewa_kernel, cudaFuncAttributeMaxDynamicSharedMemorySize, SMEM_BYTES);

    prep_kernel<<<32, 256>>>(qw, pw, nw, nb, rp);
    ewa_kernel<<<NWIN, TPB, SMEM_BYTES>>>(x, sc, out);
}

// round 9
// speedup vs baseline: 1.1350x; 1.1350x over previous
#include <cuda_runtime.h>
#include <cuda_fp16.h>

// Swin window attention, fully fused: one CTA per 8x8 window, 4 CTAs/SM.
// Q never touches smem; max-free half2 softmax via ex2.approx.f16x2 (log2-domain);
// rel-pos bias as MMA C-operand, loaded via lane-contiguous LDG.128.

#define NWIN   8192
#define TPB    256
#define LOG2E  1.4426950408889634f

// smem layout (bytes)
#define OFF_XN   0        // half [64][72]   9216  (LN output Z; later attn-out AO)
#define OFF_KV   9216     // half [64][136] 17408  (K cols 0-63, V cols 64-127)
#define SMEM_BYTES 26624

// pre-baked tables (prep kernel fills these)
__device__ unsigned g_qkvfrag[3072 * 2];   // [ntile0..23][kt0..3][lane][2]  (LN+scale folded)
__device__ unsigned g_projfrag[1024 * 2];  // [ntile0..7][kt][lane][2]
__device__ unsigned g_qkvbh[96];           // half2 qkv bias per col-pair (scale folded)
__device__ unsigned g_biasfh[2048 * 4];    // [warp][mt][quad][lane] uint4 (lane-contiguous!)

__device__ __forceinline__ unsigned packh2f(float lo, float hi) {
    __half2 h = __floats2half2_rn(lo, hi);
    return *reinterpret_cast<unsigned*>(&h);
}

__global__ void prep_kernel(const float* __restrict__ qw, const float* __restrict__ pw,
                            const float* __restrict__ nw, const float* __restrict__ nb,
                            const float* __restrict__ rpb) {
    int idx = blockIdx.x * blockDim.x + threadIdx.x;   // 32 blocks * 256 = 8192

    if (idx < 3072) {  // qkv weight fragments (norm_w + q-scale*log2e folded)
        int lane = idx & 31, kt = (idx >> 5) & 3, ntile = idx >> 7;
        int n  = ntile * 8 + (lane >> 2);
        int k0 = kt * 16 + (lane & 3) * 2;
        float sc = (n < 64) ? 0.25f * LOG2E : 1.0f;
        const float* wr = qw + n * 64;
        g_qkvfrag[idx * 2 + 0] = packh2f(wr[k0] * nw[k0] * sc,         wr[k0 + 1] * nw[k0 + 1] * sc);
        g_qkvfrag[idx * 2 + 1] = packh2f(wr[k0 + 8] * nw[k0 + 8] * sc, wr[k0 + 9] * nw[k0 + 9] * sc);
    }
    if (idx < 1024) {  // proj weight fragments
        int lane = idx & 31, kt = (idx >> 5) & 3, ntile = idx >> 7;
        int n  = ntile * 8 + (lane >> 2);
        int k0 = kt * 16 + (lane & 3) * 2;
        const float* wr = pw + n * 64;
        g_projfrag[idx * 2 + 0] = packh2f(wr[k0],     wr[k0 + 1]);
        g_projfrag[idx * 2 + 1] = packh2f(wr[k0 + 8], wr[k0 + 9]);
    }
    if (idx < 96) {    // folded LN-bias through qkv (per output col pair), scale folded
        float b0 = 0.f, b1 = 0.f;
        int c = idx * 2;
        for (int k = 0; k < 64; k++) {
            b0 += nb[k] * qw[c * 64 + k];
            b1 += nb[k] * qw[(c + 1) * 64 + k];
        }
        float sc = (c < 64) ? 0.25f * LOG2E : 1.0f;
        g_qkvbh[idx] = packh2f(b0 * sc, b1 * sc);
    }
    if (idx < 2048) {  // bias fragments: uint4 per (warp, mt, quad, lane); lane-contiguous
        int lane = idx & 31;
        int qd   = (idx >> 5) & 3;      // quad -> j pair (2*qd, 2*qd+1)
        int mt   = (idx >> 7) & 1;
        int warp = idx >> 8;
        int h  = warp >> 1;
        int m0 = (warp & 1) * 32;
        int g  = lane >> 2, tig = lane & 3;
        int rr = m0 + mt * 16 + g;
        auto bias = [&](int r, int c) {
            int dy = (r >> 3) - (c >> 3);
            int dx = (r & 7) - (c & 7);
            return rpb[((dy + 7) * 15 + (dx + 7)) * 4 + h] * LOG2E;
        };
        int c0 = (2 * qd) * 8 + tig * 2;
        int c1 = (2 * qd + 1) * 8 + tig * 2;
        g_biasfh[idx * 4 + 0] = packh2f(bias(rr, c0),     bias(rr, c0 + 1));
        g_biasfh[idx * 4 + 1] = packh2f(bias(rr + 8, c0), bias(rr + 8, c0 + 1));
        g_biasfh[idx * 4 + 2] = packh2f(bias(rr, c1),     bias(rr, c1 + 1));
        g_biasfh[idx * 4 + 3] = packh2f(bias(rr + 8, c1), bias(rr + 8, c1 + 1));
    }
}

__device__ __forceinline__ unsigned saddr(const void* p) {
    return (unsigned)__cvta_generic_to_shared(p);
}
__device__ __forceinline__ void ldsm_x4(unsigned a, unsigned& r0, unsigned& r1, unsigned& r2, unsigned& r3) {
    asm volatile("ldmatrix.sync.aligned.m8n8.x4.shared.b16 {%0,%1,%2,%3}, [%4];"
                 : "=r"(r0), "=r"(r1), "=r"(r2), "=r"(r3) : "r"(a));
}
__device__ __forceinline__ void ldsm_x4t(unsigned a, unsigned& r0, unsigned& r1, unsigned& r2, unsigned& r3) {
    asm volatile("ldmatrix.sync.aligned.m8n8.x4.trans.shared.b16 {%0,%1,%2,%3}, [%4];"
                 : "=r"(r0), "=r"(r1), "=r"(r2), "=r"(r3) : "r"(a));
}
__device__ __forceinline__ void mmah(uint2& c, unsigned a0, unsigned a1, unsigned a2, unsigned a3,
                                     unsigned b0, unsigned b1) {
    asm volatile("mma.sync.aligned.m16n8k16.row.col.f16.f16.f16.f16 "
                 "{%0,%1}, {%2,%3,%4,%5}, {%6,%7}, {%0,%1};"
                 : "+r"(c.x), "+r"(c.y)
                 : "r"(a0), "r"(a1), "r"(a2), "r"(a3), "r"(b0), "r"(b1));
}
__device__ __forceinline__ unsigned hadd2u(unsigned a, unsigned b) {
    __half2 r = __hadd2(*(__half2*)&a, *(__half2*)&b);
    return *(unsigned*)&r;
}
__device__ __forceinline__ unsigned hmul2u(unsigned a, unsigned b) {
    __half2 r = __hmul2(*(__half2*)&a, *(__half2*)&b);
    return *(unsigned*)&r;
}
__device__ __forceinline__ unsigned ex2h2(unsigned a) {
    unsigned r;
    asm("ex2.approx.f16x2 %0, %1;" : "=r"(r) : "r"(a));
    return r;
}
__device__ __forceinline__ unsigned hswap(unsigned a) {      // swap the two halves
    return __byte_perm(a, a, 0x1032);
}
__device__ __forceinline__ float2 h2f2(unsigned u) {
    return __half22float2(*(__half2*)&u);
}
__device__ __forceinline__ float hlo2f(unsigned u) {
    return __half2float(__low2half(*(__half2*)&u));
}

__global__ __launch_bounds__(256, 4)
void ewa_kernel(const float* __restrict__ x,
                const float* __restrict__ ascale,
                float* __restrict__ out) {
    extern __shared__ char smem[];
    __half* XN = (__half*)(smem + OFF_XN);   // [64][72]  Z / AO
    __half* KV = (__half*)(smem + OFF_KV);   // [64][136] K | V

    const int tid  = threadIdx.x;
    const int lane = tid & 31;
    const int warp = tid >> 5;
    const int g    = lane >> 2;
    const int tig  = lane & 3;
    const int l2   = lane & 15;

    const int win = blockIdx.x;
    const int b   = win >> 10;
    const int rem = win & 1023;
    const int wy  = rem >> 5;
    const int wx  = rem & 31;

    const int h  = warp >> 1;          // head (phases 2-3)
    const int m0 = (warp & 1) * 32;

    // ---- Phase 1: direct token-major load + in-register LayerNorm -> XN (fp16 Z) ----
    {
        int t = tid >> 2, q = tid & 3;            // token, channel quarter
        int pix = (wy * 8 + (t >> 3)) * 256 + wx * 8 + (t & 7);
        const float* base = x + (b * 64 + q * 16) * 65536 + pix;
        float v[16];
        #pragma unroll
        for (int i = 0; i < 16; i++) v[i] = base[i * 65536];
        float s = 0.f, ss = 0.f;
        #pragma unroll
        for (int i = 0; i < 16; i++) { s += v[i]; ss += v[i] * v[i]; }
        s  += __shfl_xor_sync(0xffffffffu, s, 1);  ss += __shfl_xor_sync(0xffffffffu, ss, 1);
        s  += __shfl_xor_sync(0xffffffffu, s, 2);  ss += __shfl_xor_sync(0xffffffffu, ss, 2);
        float mu   = s * (1.f / 64.f);
        float var  = ss * (1.f / 64.f) - mu * mu;
        float rstd = rsqrtf(var + 1e-5f);
        unsigned h8[8];
        #pragma unroll
        for (int i = 0; i < 8; i++)
            h8[i] = packh2f((v[2 * i] - mu) * rstd, (v[2 * i + 1] - mu) * rstd);
        uint4* dst = (uint4*)(XN + t * 72 + q * 16);
        dst[0] = make_uint4(h8[0], h8[1], h8[2], h8[3]);
        dst[1] = make_uint4(h8[4], h8[5], h8[6], h8[7]);
    }
    __syncthreads();

    // ---- Phase 2: QKV GEMM. Q for own (head, rows) stays in registers; K/V -> smem ----
    unsigned qa[2][4];   // Q as A-fragments for QK^T, per mt
    {
        uint2 qacc[2][2], kvacc[2][4];
        #pragma unroll
        for (int mt = 0; mt < 2; mt++) {
            qacc[mt][0] = make_uint2(0u, 0u); qacc[mt][1] = make_uint2(0u, 0u);
            #pragma unroll
            for (int j = 0; j < 4; j++) kvacc[mt][j] = make_uint2(0u, 0u);
        }
        #pragma unroll
        for (int kt = 0; kt < 4; kt++) {
            unsigned a[2][4];
            #pragma unroll
            for (int mt = 0; mt < 2; mt++)
                ldsm_x4(saddr(XN + (m0 + mt * 16 + l2) * 72 + kt * 16 + (lane >> 4) * 8),
                        a[mt][0], a[mt][1], a[mt][2], a[mt][3]);
            uint2 qb[2], kvb[4];
            #pragma unroll
            for (int j = 0; j < 2; j++)
                qb[j] = *(const uint2*)(g_qkvfrag + (((h * 2 + j) * 4 + kt) * 32 + lane) * 2);
            #pragma unroll
            for (int j = 0; j < 4; j++)
                kvb[j] = *(const uint2*)(g_qkvfrag + (((8 + h * 4 + j) * 4 + kt) * 32 + lane) * 2);
            #pragma unroll
            for (int mt = 0; mt < 2; mt++) {
                #pragma unroll
                for (int j = 0; j < 2; j++)
                    mmah(qacc[mt][j], a[mt][0], a[mt][1], a[mt][2], a[mt][3], qb[j].x, qb[j].y);
                #pragma unroll
                for (int j = 0; j < 4; j++)
                    mmah(kvacc[mt][j], a[mt][0], a[mt][1], a[mt][2], a[mt][3], kvb[j].x, kvb[j].y);
            }
        }
        // Q: D-frag (+bias) == A-frag for QK^T
        unsigned bq0 = g_qkvbh[h * 8 + tig];
        unsigned bq1 = g_qkvbh[h * 8 + 4 + tig];
        #pragma unroll
        for (int mt = 0; mt < 2; mt++) {
            qa[mt][0] = hadd2u(qacc[mt][0].x, bq0);
            qa[mt][1] = hadd2u(qacc[mt][0].y, bq0);
            qa[mt][2] = hadd2u(qacc[mt][1].x, bq1);
            qa[mt][3] = hadd2u(qacc[mt][1].y, bq1);
        }
        // K/V -> smem (smem col = global col - 64)
        #pragma unroll
        for (int j = 0; j < 4; j++) {
            int col = h * 32 + j * 8 + tig * 2;
            unsigned bh = g_qkvbh[32 + h * 16 + j * 4 + tig];
            #pragma unroll
            for (int mt = 0; mt < 2; mt++) {
                int row = m0 + mt * 16 + g;
                *(unsigned*)(KV + row * 136 + col)       = hadd2u(kvacc[mt][j].x, bh);
                *(unsigned*)(KV + (row + 8) * 136 + col) = hadd2u(kvacc[mt][j].y, bh);
            }
        }
    }
    __syncthreads();

    // ---- Phase 3: attention (log2-domain, max-free half2 softmax, bias as C-init) ----
    {
        unsigned kb[8][2];
        #pragma unroll
        for (int jp = 0; jp < 4; jp++) {        // K fragments via ldmatrix.x4 (2 n-tiles each)
            unsigned r0, r1, r2, r3;
            int j  = (lane >> 4);               // n-tile within pair
            int kh = (lane >> 3) & 1;
            ldsm_x4(saddr(KV + ((jp * 2 + j) * 8 + (lane & 7)) * 136 + h * 16 + kh * 8),
                    r0, r1, r2, r3);
            kb[jp * 2 + 0][0] = r0; kb[jp * 2 + 0][1] = r1;
            kb[jp * 2 + 1][0] = r2; kb[jp * 2 + 1][1] = r3;
        }

        #pragma unroll
        for (int mt = 0; mt < 2; mt++) {
            // bias fragments: 4 lane-contiguous LDG.128
            const uint4* bfp = (const uint4*)(g_biasfh) + (warp * 2 + mt) * 128 + lane;
            uint2 s[8];
            #pragma unroll
            for (int qd = 0; qd < 4; qd++) {
                uint4 bv = bfp[qd * 32];
                s[2 * qd].x = bv.x;     s[2 * qd].y = bv.y;
                s[2 * qd + 1].x = bv.z; s[2 * qd + 1].y = bv.w;
            }
            #pragma unroll
            for (int j = 0; j < 8; j++)
                mmah(s[j], qa[mt][0], qa[mt][1], qa[mt][2], qa[mt][3], kb[j][0], kb[j][1]);

            // max-free: p = 2^l directly (logits bounded, fp16-safe)
            unsigned sum0 = 0u, sum1 = 0u;
            #pragma unroll
            for (int j = 0; j < 8; j++) {
                s[j].x = ex2h2(s[j].x);
                s[j].y = ex2h2(s[j].y);
                sum0 = hadd2u(sum0, s[j].x);
                sum1 = hadd2u(sum1, s[j].y);
            }

            // AV MMAs issued before the sum shuffle chain (independent)
            uint2 o[2];
            o[0].x = o[0].y = o[1].x = o[1].y = 0u;
            #pragma unroll
            for (int kt = 0; kt < 4; kt++) {
                unsigned v0, v1, v2, v3;
                ldsm_x4t(saddr(KV + (kt * 16 + (lane & 7) + ((lane >> 3) & 1) * 8) * 136
                               + 64 + h * 16 + (lane >> 4) * 8),
                         v0, v1, v2, v3);
                mmah(o[0], s[2 * kt].x, s[2 * kt].y, s[2 * kt + 1].x, s[2 * kt + 1].y, v0, v1);
                mmah(o[1], s[2 * kt].x, s[2 * kt].y, s[2 * kt + 1].x, s[2 * kt + 1].y, v2, v3);
            }

            sum0 = hadd2u(sum0, __shfl_xor_sync(0xffffffffu, sum0, 1));
            sum0 = hadd2u(sum0, __shfl_xor_sync(0xffffffffu, sum0, 2));
            sum0 = hadd2u(sum0, hswap(sum0));
            sum1 = hadd2u(sum1, __shfl_xor_sync(0xffffffffu, sum1, 1));
            sum1 = hadd2u(sum1, __shfl_xor_sync(0xffffffffu, sum1, 2));
            sum1 = hadd2u(sum1, hswap(sum1));

            float f0 = __fdividef(1.f, hlo2f(sum0));
            float f1 = __fdividef(1.f, hlo2f(sum1));
            unsigned i0 = packh2f(f0, f0);
            unsigned i1 = packh2f(f1, f1);
            #pragma unroll
            for (int nt = 0; nt < 2; nt++) {
                int row = m0 + mt * 16 + g;
                int col = h * 16 + nt * 8 + tig * 2;
                *(unsigned*)(XN + row * 72 + col)       = hmul2u(o[nt].x, i0);
                *(unsigned*)(XN + (row + 8) * 72 + col) = hmul2u(o[nt].y, i1);
            }
        }
    }
    __syncthreads();

    // ---- Phase 4: proj GEMM [64,64]x[64,64] + residual + write out (fp16 acc) ----
    {
        const int ntb = (warp >> 1) * 2;      // ntile base (8-col tiles)
        uint2 acc[2][2];
        acc[0][0] = make_uint2(0u, 0u); acc[0][1] = make_uint2(0u, 0u);
        acc[1][0] = make_uint2(0u, 0u); acc[1][1] = make_uint2(0u, 0u);
        #pragma unroll
        for (int kt = 0; kt < 4; kt++) {
            unsigned a[2][4];
            #pragma unroll
            for (int mt = 0; mt < 2; mt++)
                ldsm_x4(saddr(XN + (m0 + mt * 16 + l2) * 72 + kt * 16 + (lane >> 4) * 8),
                        a[mt][0], a[mt][1], a[mt][2], a[mt][3]);
            uint2 bf[2];
            #pragma unroll
            for (int nt = 0; nt < 2; nt++)
                bf[nt] = *(const uint2*)(g_projfrag + (((ntb + nt) * 4 + kt) * 32 + lane) * 2);
            #pragma unroll
            for (int mt = 0; mt < 2; mt++)
                #pragma unroll
                for (int nt = 0; nt < 2; nt++)
                    mmah(acc[mt][nt], a[mt][0], a[mt][1], a[mt][2], a[mt][3], bf[nt].x, bf[nt].y);
        }
        float ssc = ascale[0];
        #pragma unroll
        for (int mt = 0; mt < 2; mt++)
            #pragma unroll
            for (int nt = 0; nt < 2; nt++) {
                int ch = (ntb + nt) * 8 + tig * 2;
                float2 lo = h2f2(acc[mt][nt].x);   // rows m0+mt*16+g
                float2 hi = h2f2(acc[mt][nt].y);   // rows +8
                #pragma unroll
                for (int hf = 0; hf < 2; hf++) {
                    int row = m0 + mt * 16 + g + hf * 8;
                    float2 v = hf ? hi : lo;
                    int gi0 = ((b * 64 + ch) * 256 + wy * 8 + (row >> 3)) * 256 + wx * 8 + (row & 7);
                    int gi1 = gi0 + 65536;   // ch+1
                    out[gi0] = x[gi0] + ssc * v.x;
                    out[gi1] = x[gi1] + ssc * v.y;
                }
            }
    }
}

extern "C" void kernel_launch(void* const* d_in, const int* in_sizes, int n_in,
                              void* d_out, int out_size) {
    const float* x  = (const float*)d_in[0];
    const float* nw = (const float*)d_in[1];
    const float* nb = (const float*)d_in[2];
    const float* qw = (const float*)d_in[3];
    const float* pw = (const float*)d_in[4];
    const float* sc = (const float*)d_in[5];
    const float* rp = (const float*)d_in[6];
    float* out = (float*)d_out;

    cudaFuncSetAttribute(ewa_kernel, cudaFuncAttributeMaxDynamicSharedMemorySize, SMEM_BYTES);

    prep_kernel<<<32, 256>>>(qw, pw, nw, nb, rp);
    ewa_kernel<<<NWIN, TPB, SMEM_BYTES>>>(x, sc, out);
}

// round 10
// speedup vs baseline: 1.1452x; 1.0089x over previous
#include <cuda_runtime.h>
#include <cuda_fp16.h>

// Swin window attention, fully fused: one CTA per 8x8 window, 4 CTAs/SM.
// Q never touches smem; max-free half2 softmax via ex2.approx.f16x2 (log2-domain);
// rel-pos bias as MMA C-operand; row-sums via ones-column MMA (no shuffle reduction).

#define NWIN   8192
#define TPB    256
#define LOG2E  1.4426950408889634f
#define ONESH2 0x3C003C00u

// smem layout (bytes)
#define OFF_XN   0        // half [64][72]   9216  (LN output Z; later attn-out AO)
#define OFF_KV   9216     // half [64][136] 17408  (K cols 0-63, V cols 64-127)
#define SMEM_BYTES 26624

// pre-baked tables (prep kernel fills these)
__device__ unsigned g_qkvfrag[3072 * 2];   // [ntile0..23][kt0..3][lane][2]  (LN+scale folded)
__device__ unsigned g_projfrag[1024 * 2];  // [ntile0..7][kt][lane][2]
__device__ unsigned g_qkvbh[96];           // half2 qkv bias per col-pair (scale folded)
__device__ unsigned g_biasfh[2048 * 4];    // [warp][mt][quad][lane] uint4 (lane-contiguous)

__device__ __forceinline__ unsigned packh2f(float lo, float hi) {
    __half2 h = __floats2half2_rn(lo, hi);
    return *reinterpret_cast<unsigned*>(&h);
}

__global__ void prep_kernel(const float* __restrict__ qw, const float* __restrict__ pw,
                            const float* __restrict__ nw, const float* __restrict__ nb,
                            const float* __restrict__ rpb) {
    int idx = blockIdx.x * blockDim.x + threadIdx.x;   // 32 blocks * 256 = 8192

    if (idx < 3072) {  // qkv weight fragments (norm_w + q-scale*log2e folded)
        int lane = idx & 31, kt = (idx >> 5) & 3, ntile = idx >> 7;
        int n  = ntile * 8 + (lane >> 2);
        int k0 = kt * 16 + (lane & 3) * 2;
        float sc = (n < 64) ? 0.25f * LOG2E : 1.0f;
        const float* wr = qw + n * 64;
        g_qkvfrag[idx * 2 + 0] = packh2f(wr[k0] * nw[k0] * sc,         wr[k0 + 1] * nw[k0 + 1] * sc);
        g_qkvfrag[idx * 2 + 1] = packh2f(wr[k0 + 8] * nw[k0 + 8] * sc, wr[k0 + 9] * nw[k0 + 9] * sc);
    }
    if (idx < 1024) {  // proj weight fragments
        int lane = idx & 31, kt = (idx >> 5) & 3, ntile = idx >> 7;
        int n  = ntile * 8 + (lane >> 2);
        int k0 = kt * 16 + (lane & 3) * 2;
        const float* wr = pw + n * 64;
        g_projfrag[idx * 2 + 0] = packh2f(wr[k0],     wr[k0 + 1]);
        g_projfrag[idx * 2 + 1] = packh2f(wr[k0 + 8], wr[k0 + 9]);
    }
    if (idx < 96) {    // folded LN-bias through qkv (per output col pair), scale folded
        float b0 = 0.f, b1 = 0.f;
        int c = idx * 2;
        for (int k = 0; k < 64; k++) {
            b0 += nb[k] * qw[c * 64 + k];
            b1 += nb[k] * qw[(c + 1) * 64 + k];
        }
        float sc = (c < 64) ? 0.25f * LOG2E : 1.0f;
        g_qkvbh[idx] = packh2f(b0 * sc, b1 * sc);
    }
    if (idx < 2048) {  // bias fragments: uint4 per (warp, mt, quad, lane); lane-contiguous
        int lane = idx & 31;
        int qd   = (idx >> 5) & 3;      // quad -> j pair (2*qd, 2*qd+1)
        int mt   = (idx >> 7) & 1;
        int warp = idx >> 8;
        int h  = warp >> 1;
        int m0 = (warp & 1) * 32;
        int g  = lane >> 2, tig = lane & 3;
        int rr = m0 + mt * 16 + g;
        auto bias = [&](int r, int c) {
            int dy = (r >> 3) - (c >> 3);
            int dx = (r & 7) - (c & 7);
            return rpb[((dy + 7) * 15 + (dx + 7)) * 4 + h] * LOG2E;
        };
        int c0 = (2 * qd) * 8 + tig * 2;
        int c1 = (2 * qd + 1) * 8 + tig * 2;
        g_biasfh[idx * 4 + 0] = packh2f(bias(rr, c0),     bias(rr, c0 + 1));
        g_biasfh[idx * 4 + 1] = packh2f(bias(rr + 8, c0), bias(rr + 8, c0 + 1));
        g_biasfh[idx * 4 + 2] = packh2f(bias(rr, c1),     bias(rr, c1 + 1));
        g_biasfh[idx * 4 + 3] = packh2f(bias(rr + 8, c1), bias(rr + 8, c1 + 1));
    }
}

__device__ __forceinline__ unsigned saddr(const void* p) {
    return (unsigned)__cvta_generic_to_shared(p);
}
__device__ __forceinline__ void ldsm_x4(unsigned a, unsigned& r0, unsigned& r1, unsigned& r2, unsigned& r3) {
    asm volatile("ldmatrix.sync.aligned.m8n8.x4.shared.b16 {%0,%1,%2,%3}, [%4];"
                 : "=r"(r0), "=r"(r1), "=r"(r2), "=r"(r3) : "r"(a));
}
__device__ __forceinline__ void ldsm_x4t(unsigned a, unsigned& r0, unsigned& r1, unsigned& r2, unsigned& r3) {
    asm volatile("ldmatrix.sync.aligned.m8n8.x4.trans.shared.b16 {%0,%1,%2,%3}, [%4];"
                 : "=r"(r0), "=r"(r1), "=r"(r2), "=r"(r3) : "r"(a));
}
__device__ __forceinline__ void mmah(uint2& c, unsigned a0, unsigned a1, unsigned a2, unsigned a3,
                                     unsigned b0, unsigned b1) {
    asm volatile("mma.sync.aligned.m16n8k16.row.col.f16.f16.f16.f16 "
                 "{%0,%1}, {%2,%3,%4,%5}, {%6,%7}, {%0,%1};"
                 : "+r"(c.x), "+r"(c.y)
                 : "r"(a0), "r"(a1), "r"(a2), "r"(a3), "r"(b0), "r"(b1));
}
__device__ __forceinline__ unsigned hadd2u(unsigned a, unsigned b) {
    __half2 r = __hadd2(*(__half2*)&a, *(__half2*)&b);
    return *(unsigned*)&r;
}
__device__ __forceinline__ unsigned hmul2u(unsigned a, unsigned b) {
    __half2 r = __hmul2(*(__half2*)&a, *(__half2*)&b);
    return *(unsigned*)&r;
}
__device__ __forceinline__ unsigned ex2h2(unsigned a) {
    unsigned r;
    asm("ex2.approx.f16x2 %0, %1;" : "=r"(r) : "r"(a));
    return r;
}
__device__ __forceinline__ float2 h2f2(unsigned u) {
    return __half22float2(*(__half2*)&u);
}
__device__ __forceinline__ float hlo2f(unsigned u) {
    return __half2float(__low2half(*(__half2*)&u));
}

__global__ __launch_bounds__(256, 4)
void ewa_kernel(const float* __restrict__ x,
                const float* __restrict__ ascale,
                float* __restrict__ out) {
    extern __shared__ char smem[];
    __half* XN = (__half*)(smem + OFF_XN);   // [64][72]  Z / AO
    __half* KV = (__half*)(smem + OFF_KV);   // [64][136] K | V

    const int tid  = threadIdx.x;
    const int lane = tid & 31;
    const int warp = tid >> 5;
    const int g    = lane >> 2;
    const int tig  = lane & 3;
    const int l2   = lane & 15;

    const int win = blockIdx.x;
    const int b   = win >> 10;
    const int rem = win & 1023;
    const int wy  = rem >> 5;
    const int wx  = rem & 31;

    const int h  = warp >> 1;          // head (phases 2-3)
    const int m0 = (warp & 1) * 32;

    // ---- Phase 1: direct token-major load + in-register LayerNorm -> XN (fp16 Z) ----
    {
        int t = tid >> 2, q = tid & 3;            // token, channel quarter
        int pix = (wy * 8 + (t >> 3)) * 256 + wx * 8 + (t & 7);
        const float* base = x + (b * 64 + q * 16) * 65536 + pix;
        float v[16];
        #pragma unroll
        for (int i = 0; i < 16; i++) v[i] = base[i * 65536];
        float s = 0.f, ss = 0.f;
        #pragma unroll
        for (int i = 0; i < 16; i++) { s += v[i]; ss += v[i] * v[i]; }
        s  += __shfl_xor_sync(0xffffffffu, s, 1);  ss += __shfl_xor_sync(0xffffffffu, ss, 1);
        s  += __shfl_xor_sync(0xffffffffu, s, 2);  ss += __shfl_xor_sync(0xffffffffu, ss, 2);
        float mu   = s * (1.f / 64.f);
        float var  = ss * (1.f / 64.f) - mu * mu;
        float rstd = rsqrtf(var + 1e-5f);
        unsigned h8[8];
        #pragma unroll
        for (int i = 0; i < 8; i++)
            h8[i] = packh2f((v[2 * i] - mu) * rstd, (v[2 * i + 1] - mu) * rstd);
        uint4* dst = (uint4*)(XN + t * 72 + q * 16);
        dst[0] = make_uint4(h8[0], h8[1], h8[2], h8[3]);
        dst[1] = make_uint4(h8[4], h8[5], h8[6], h8[7]);
    }
    __syncthreads();

    // ---- Phase 2: QKV GEMM. Q for own (head, rows) stays in registers; K/V -> smem ----
    unsigned qa[2][4];   // Q as A-fragments for QK^T, per mt
    {
        uint2 qacc[2][2], kvacc[2][4];
        #pragma unroll
        for (int mt = 0; mt < 2; mt++) {
            qacc[mt][0] = make_uint2(0u, 0u); qacc[mt][1] = make_uint2(0u, 0u);
            #pragma unroll
            for (int j = 0; j < 4; j++) kvacc[mt][j] = make_uint2(0u, 0u);
        }
        #pragma unroll
        for (int kt = 0; kt < 4; kt++) {
            unsigned a[2][4];
            #pragma unroll
            for (int mt = 0; mt < 2; mt++)
                ldsm_x4(saddr(XN + (m0 + mt * 16 + l2) * 72 + kt * 16 + (lane >> 4) * 8),
                        a[mt][0], a[mt][1], a[mt][2], a[mt][3]);
            uint2 qb[2], kvb[4];
            #pragma unroll
            for (int j = 0; j < 2; j++)
                qb[j] = *(const uint2*)(g_qkvfrag + (((h * 2 + j) * 4 + kt) * 32 + lane) * 2);
            #pragma unroll
            for (int j = 0; j < 4; j++)
                kvb[j] = *(const uint2*)(g_qkvfrag + (((8 + h * 4 + j) * 4 + kt) * 32 + lane) * 2);
            #pragma unroll
            for (int mt = 0; mt < 2; mt++) {
                #pragma unroll
                for (int j = 0; j < 2; j++)
                    mmah(qacc[mt][j], a[mt][0], a[mt][1], a[mt][2], a[mt][3], qb[j].x, qb[j].y);
                #pragma unroll
                for (int j = 0; j < 4; j++)
                    mmah(kvacc[mt][j], a[mt][0], a[mt][1], a[mt][2], a[mt][3], kvb[j].x, kvb[j].y);
            }
        }
        // Q: D-frag (+bias) == A-frag for QK^T
        unsigned bq0 = g_qkvbh[h * 8 + tig];
        unsigned bq1 = g_qkvbh[h * 8 + 4 + tig];
        #pragma unroll
        for (int mt = 0; mt < 2; mt++) {
            qa[mt][0] = hadd2u(qacc[mt][0].x, bq0);
            qa[mt][1] = hadd2u(qacc[mt][0].y, bq0);
            qa[mt][2] = hadd2u(qacc[mt][1].x, bq1);
            qa[mt][3] = hadd2u(qacc[mt][1].y, bq1);
        }
        // K/V -> smem (smem col = global col - 64)
        #pragma unroll
        for (int j = 0; j < 4; j++) {
            int col = h * 32 + j * 8 + tig * 2;
            unsigned bh = g_qkvbh[32 + h * 16 + j * 4 + tig];
            #pragma unroll
            for (int mt = 0; mt < 2; mt++) {
                int row = m0 + mt * 16 + g;
                *(unsigned*)(KV + row * 136 + col)       = hadd2u(kvacc[mt][j].x, bh);
                *(unsigned*)(KV + (row + 8) * 136 + col) = hadd2u(kvacc[mt][j].y, bh);
            }
        }
    }
    __syncthreads();

    // ---- Phase 3: attention (log2-domain, max-free half2 softmax, bias as C-init,
    //               row sums via ones-column MMA) ----
    {
        unsigned kb[8][2];
        #pragma unroll
        for (int jp = 0; jp < 4; jp++) {        // K fragments via ldmatrix.x4 (2 n-tiles each)
            unsigned r0, r1, r2, r3;
            int j  = (lane >> 4);               // n-tile within pair
            int kh = (lane >> 3) & 1;
            ldsm_x4(saddr(KV + ((jp * 2 + j) * 8 + (lane & 7)) * 136 + h * 16 + kh * 8),
                    r0, r1, r2, r3);
            kb[jp * 2 + 0][0] = r0; kb[jp * 2 + 0][1] = r1;
            kb[jp * 2 + 1][0] = r2; kb[jp * 2 + 1][1] = r3;
        }

        #pragma unroll
        for (int mt = 0; mt < 2; mt++) {
            // bias fragments: 4 lane-contiguous LDG.128
            const uint4* bfp = (const uint4*)(g_biasfh) + (warp * 2 + mt) * 128 + lane;
            uint2 s[8];
            #pragma unroll
            for (int qd = 0; qd < 4; qd++) {
                uint4 bv = bfp[qd * 32];
                s[2 * qd].x = bv.x;     s[2 * qd].y = bv.y;
                s[2 * qd + 1].x = bv.z; s[2 * qd + 1].y = bv.w;
            }
            #pragma unroll
            for (int j = 0; j < 8; j++)
                mmah(s[j], qa[mt][0], qa[mt][1], qa[mt][2], qa[mt][3], kb[j][0], kb[j][1]);

            // max-free: p = 2^l directly (logits bounded, fp16-safe)
            #pragma unroll
            for (int j = 0; j < 8; j++) {
                s[j].x = ex2h2(s[j].x);
                s[j].y = ex2h2(s[j].y);
            }

            // AV + row-sum (P @ ones) via MMA; o2.x/.y hold sums for rows g / g+8
            uint2 o[2], o2;
            o[0].x = o[0].y = o[1].x = o[1].y = 0u;
            o2.x = o2.y = 0u;
            #pragma unroll
            for (int kt = 0; kt < 4; kt++) {
                unsigned v0, v1, v2, v3;
                ldsm_x4t(saddr(KV + (kt * 16 + (lane & 7) + ((lane >> 3) & 1) * 8) * 136
                               + 64 + h * 16 + (lane >> 4) * 8),
                         v0, v1, v2, v3);
                mmah(o[0], s[2 * kt].x, s[2 * kt].y, s[2 * kt + 1].x, s[2 * kt + 1].y, v0, v1);
                mmah(o[1], s[2 * kt].x, s[2 * kt].y, s[2 * kt + 1].x, s[2 * kt + 1].y, v2, v3);
                mmah(o2,   s[2 * kt].x, s[2 * kt].y, s[2 * kt + 1].x, s[2 * kt + 1].y,
                     ONESH2, ONESH2);
            }

            float f0 = __fdividef(1.f, hlo2f(o2.x));
            float f1 = __fdividef(1.f, hlo2f(o2.y));
            unsigned i0 = packh2f(f0, f0);
            unsigned i1 = packh2f(f1, f1);
            #pragma unroll
            for (int nt = 0; nt < 2; nt++) {
                int row = m0 + mt * 16 + g;
                int col = h * 16 + nt * 8 + tig * 2;
                *(unsigned*)(XN + row * 72 + col)       = hmul2u(o[nt].x, i0);
                *(unsigned*)(XN + (row + 8) * 72 + col) = hmul2u(o[nt].y, i1);
            }
        }
    }
    __syncthreads();

    // ---- Phase 4: proj GEMM [64,64]x[64,64] + residual + write out (fp16 acc) ----
    {
        const int ntb = (warp >> 1) * 2;      // ntile base (8-col tiles)

        // hoist all proj B-fragments (overlap LDG latency with ldsm/MMA chain)
        uint2 bf[4][2];
        #pragma unroll
        for (int kt = 0; kt < 4; kt++)
            #pragma unroll
            for (int nt = 0; nt < 2; nt++)
                bf[kt][nt] = *(const uint2*)(g_projfrag + (((ntb + nt) * 4 + kt) * 32 + lane) * 2);

        uint2 acc[2][2];
        acc[0][0] = make_uint2(0u, 0u); acc[0][1] = make_uint2(0u, 0u);
        acc[1][0] = make_uint2(0u, 0u); acc[1][1] = make_uint2(0u, 0u);
        #pragma unroll
        for (int kt = 0; kt < 4; kt++) {
            unsigned a[2][4];
            #pragma unroll
            for (int mt = 0; mt < 2; mt++)
                ldsm_x4(saddr(XN + (m0 + mt * 16 + l2) * 72 + kt * 16 + (lane >> 4) * 8),
                        a[mt][0], a[mt][1], a[mt][2], a[mt][3]);
            #pragma unroll
            for (int mt = 0; mt < 2; mt++)
                #pragma unroll
                for (int nt = 0; nt < 2; nt++)
                    mmah(acc[mt][nt], a[mt][0], a[mt][1], a[mt][2], a[mt][3],
                         bf[kt][nt].x, bf[kt][nt].y);
        }
        float ssc = ascale[0];
        #pragma unroll
        for (int mt = 0; mt < 2; mt++)
            #pragma unroll
            for (int nt = 0; nt < 2; nt++) {
                int ch = (ntb + nt) * 8 + tig * 2;
                float2 lo = h2f2(acc[mt][nt].x);   // rows m0+mt*16+g
                float2 hi = h2f2(acc[mt][nt].y);   // rows +8
                #pragma unroll
                for (int hf = 0; hf < 2; hf++) {
                    int row = m0 + mt * 16 + g + hf * 8;
                    float2 v = hf ? hi : lo;
                    int gi0 = ((b * 64 + ch) * 256 + wy * 8 + (row >> 3)) * 256 + wx * 8 + (row & 7);
                    int gi1 = gi0 + 65536;   // ch+1
                    out[gi0] = x[gi0] + ssc * v.x;
                    out[gi1] = x[gi1] + ssc * v.y;
                }
            }
    }
}

extern "C" void kernel_launch(void* const* d_in, const int* in_sizes, int n_in,
                              void* d_out, int out_size) {
    const float* x  = (const float*)d_in[0];
    const float* nw = (const float*)d_in[1];
    const float* nb = (const float*)d_in[2];
    const float* qw = (const float*)d_in[3];
    const float* pw = (const float*)d_in[4];
    const float* sc = (const float*)d_in[5];
    const float* rp = (const float*)d_in[6];
    float* out = (float*)d_out;

    cudaFuncSetAttribute(ewa_kernel, cudaFuncAttributeMaxDynamicSharedMemorySize, SMEM_BYTES);

    prep_kernel<<<32, 256>>>(qw, pw, nw, nb, rp);
    ewa_kernel<<<NWIN, TPB, SMEM_BYTES>>>(x, sc, out);
}

// round 11
// speedup vs baseline: 1.3024x; 1.1373x over previous
#include <cuda_runtime.h>
#include <cuda_fp16.h>

// Swin window attention: one CTA per PAIR of horizontally-adjacent 8x8 windows.
// 64B-coalesced global in/out; staged epilogue; fragment tables stay L1-resident.
// Q never touches smem; max-free half2 softmax (log2-domain); bias as MMA C-init;
// row sums via ones-column MMA.

#define NPAIR  4096
#define TPB    256
#define LOG2E  1.4426950408889634f
#define ONESH2 0x3C003C00u

// smem layout (bytes)
#define OFF_XN   0        // half [128][72] 18432  (Z both windows; later AO)
#define OFF_KV   18432    // half [64][136] K|V per window (17408) / staging [128][72] (18432)
#define SMEM_BYTES 36864

// pre-baked tables (prep kernel fills these)
__device__ unsigned g_qkvfrag[3072 * 2];   // [ntile0..23][kt0..3][lane][2]  (LN+scale folded)
__device__ unsigned g_projfrag[1024 * 2];  // [ntile0..7][kt][lane][2]
__device__ unsigned g_qkvbh[96];           // half2 qkv bias per col-pair (scale folded)
__device__ unsigned g_biasfh[2048 * 4];    // [warp][mt][quad][lane] uint4 (lane-contiguous)

__device__ __forceinline__ unsigned packh2f(float lo, float hi) {
    __half2 h = __floats2half2_rn(lo, hi);
    return *reinterpret_cast<unsigned*>(&h);
}

__global__ void prep_kernel(const float* __restrict__ qw, const float* __restrict__ pw,
                            const float* __restrict__ nw, const float* __restrict__ nb,
                            const float* __restrict__ rpb) {
    int idx = blockIdx.x * blockDim.x + threadIdx.x;   // 32 blocks * 256 = 8192

    if (idx < 3072) {  // qkv weight fragments (norm_w + q-scale*log2e folded)
        int lane = idx & 31, kt = (idx >> 5) & 3, ntile = idx >> 7;
        int n  = ntile * 8 + (lane >> 2);
        int k0 = kt * 16 + (lane & 3) * 2;
        float sc = (n < 64) ? 0.25f * LOG2E : 1.0f;
        const float* wr = qw + n * 64;
        g_qkvfrag[idx * 2 + 0] = packh2f(wr[k0] * nw[k0] * sc,         wr[k0 + 1] * nw[k0 + 1] * sc);
        g_qkvfrag[idx * 2 + 1] = packh2f(wr[k0 + 8] * nw[k0 + 8] * sc, wr[k0 + 9] * nw[k0 + 9] * sc);
    }
    if (idx < 1024) {  // proj weight fragments
        int lane = idx & 31, kt = (idx >> 5) & 3, ntile = idx >> 7;
        int n  = ntile * 8 + (lane >> 2);
        int k0 = kt * 16 + (lane & 3) * 2;
        const float* wr = pw + n * 64;
        g_projfrag[idx * 2 + 0] = packh2f(wr[k0],     wr[k0 + 1]);
        g_projfrag[idx * 2 + 1] = packh2f(wr[k0 + 8], wr[k0 + 9]);
    }
    if (idx < 96) {    // folded LN-bias through qkv (per output col pair), scale folded
        float b0 = 0.f, b1 = 0.f;
        int c = idx * 2;
        for (int k = 0; k < 64; k++) {
            b0 += nb[k] * qw[c * 64 + k];
            b1 += nb[k] * qw[(c + 1) * 64 + k];
        }
        float sc = (c < 64) ? 0.25f * LOG2E : 1.0f;
        g_qkvbh[idx] = packh2f(b0 * sc, b1 * sc);
    }
    if (idx < 2048) {  // bias fragments: uint4 per (warp, mt, quad, lane); lane-contiguous
        int lane = idx & 31;
        int qd   = (idx >> 5) & 3;      // quad -> j pair (2*qd, 2*qd+1)
        int mt   = (idx >> 7) & 1;
        int warp = idx >> 8;
        int h  = warp >> 1;
        int m0 = (warp & 1) * 32;
        int g  = lane >> 2, tig = lane & 3;
        int rr = m0 + mt * 16 + g;
        auto bias = [&](int r, int c) {
            int dy = (r >> 3) - (c >> 3);
            int dx = (r & 7) - (c & 7);
            return rpb[((dy + 7) * 15 + (dx + 7)) * 4 + h] * LOG2E;
        };
        int c0 = (2 * qd) * 8 + tig * 2;
        int c1 = (2 * qd + 1) * 8 + tig * 2;
        g_biasfh[idx * 4 + 0] = packh2f(bias(rr, c0),     bias(rr, c0 + 1));
        g_biasfh[idx * 4 + 1] = packh2f(bias(rr + 8, c0), bias(rr + 8, c0 + 1));
        g_biasfh[idx * 4 + 2] = packh2f(bias(rr, c1),     bias(rr, c1 + 1));
        g_biasfh[idx * 4 + 3] = packh2f(bias(rr + 8, c1), bias(rr + 8, c1 + 1));
    }
}

__device__ __forceinline__ unsigned saddr(const void* p) {
    return (unsigned)__cvta_generic_to_shared(p);
}
__device__ __forceinline__ void ldsm_x4(unsigned a, unsigned& r0, unsigned& r1, unsigned& r2, unsigned& r3) {
    asm volatile("ldmatrix.sync.aligned.m8n8.x4.shared.b16 {%0,%1,%2,%3}, [%4];"
                 : "=r"(r0), "=r"(r1), "=r"(r2), "=r"(r3) : "r"(a));
}
__device__ __forceinline__ void ldsm_x4t(unsigned a, unsigned& r0, unsigned& r1, unsigned& r2, unsigned& r3) {
    asm volatile("ldmatrix.sync.aligned.m8n8.x4.trans.shared.b16 {%0,%1,%2,%3}, [%4];"
                 : "=r"(r0), "=r"(r1), "=r"(r2), "=r"(r3) : "r"(a));
}
__device__ __forceinline__ void mmah(uint2& c, unsigned a0, unsigned a1, unsigned a2, unsigned a3,
                                     unsigned b0, unsigned b1) {
    asm volatile("mma.sync.aligned.m16n8k16.row.col.f16.f16.f16.f16 "
                 "{%0,%1}, {%2,%3,%4,%5}, {%6,%7}, {%0,%1};"
                 : "+r"(c.x), "+r"(c.y)
                 : "r"(a0), "r"(a1), "r"(a2), "r"(a3), "r"(b0), "r"(b1));
}
__device__ __forceinline__ unsigned hadd2u(unsigned a, unsigned b) {
    __half2 r = __hadd2(*(__half2*)&a, *(__half2*)&b);
    return *(unsigned*)&r;
}
__device__ __forceinline__ unsigned ex2h2(unsigned a) {
    unsigned r;
    asm("ex2.approx.f16x2 %0, %1;" : "=r"(r) : "r"(a));
    return r;
}
__device__ __forceinline__ unsigned hmul2u(unsigned a, unsigned b) {
    __half2 r = __hmul2(*(__half2*)&a, *(__half2*)&b);
    return *(unsigned*)&r;
}
__device__ __forceinline__ float2 h2f2(unsigned u) {
    return __half22float2(*(__half2*)&u);
}
__device__ __forceinline__ float hlo2f(unsigned u) {
    return __half2float(__low2half(*(__half2*)&u));
}

__global__ __launch_bounds__(256, 4)
void ewa_kernel(const float* __restrict__ x,
                const float* __restrict__ ascale,
                float* __restrict__ out) {
    extern __shared__ char smem[];
    __half* XN = (__half*)(smem + OFF_XN);   // [128][72]  Z / AO (both windows)
    __half* KV = (__half*)(smem + OFF_KV);   // [64][136] K|V (per window) / staging [128][72]

    const int tid  = threadIdx.x;
    const int lane = tid & 31;
    const int warp = tid >> 5;
    const int g    = lane >> 2;
    const int tig  = lane & 3;
    const int l2   = lane & 15;

    const int pid = blockIdx.x;
    const int b   = pid >> 9;
    const int rem = pid & 511;
    const int wy  = rem >> 4;      // 0..31
    const int wpx = rem & 15;      // window-pair column: px base = wpx*16

    const int h  = warp >> 1;      // head (phases 2-3)
    const int m0 = (warp & 1) * 32;

    // ---- Phase 1: 64B-coalesced load of both windows + in-register LayerNorm ----
    {
        int r    = warp;           // pixel row within window (0..7)
        int px16 = lane >> 1;      // 0..15 across the pair
        int hq   = lane & 1;       // channel half (0: c 0-31, 1: c 32-63)
        int w    = px16 >> 3;
        int tp   = w * 64 + r * 8 + (px16 & 7);    // token index in pair coords
        const float* base = x + (b * 64 + hq * 32) * 65536
                              + (wy * 8 + r) * 256 + wpx * 16 + px16;
        float v[32];
        #pragma unroll
        for (int i = 0; i < 32; i++) v[i] = base[i * 65536];
        float s = 0.f, ss = 0.f;
        #pragma unroll
        for (int i = 0; i < 32; i++) { s += v[i]; ss += v[i] * v[i]; }
        s  += __shfl_xor_sync(0xffffffffu, s, 1);
        ss += __shfl_xor_sync(0xffffffffu, ss, 1);
        float mu   = s * (1.f / 64.f);
        float var  = ss * (1.f / 64.f) - mu * mu;
        float rstd = rsqrtf(var + 1e-5f);
        unsigned hh[16];
        #pragma unroll
        for (int i = 0; i < 16; i++)
            hh[i] = packh2f((v[2 * i] - mu) * rstd, (v[2 * i + 1] - mu) * rstd);
        uint4* dst = (uint4*)(XN + tp * 72 + hq * 32);
        dst[0] = make_uint4(hh[0],  hh[1],  hh[2],  hh[3]);
        dst[1] = make_uint4(hh[4],  hh[5],  hh[6],  hh[7]);
        dst[2] = make_uint4(hh[8],  hh[9],  hh[10], hh[11]);
        dst[3] = make_uint4(hh[12], hh[13], hh[14], hh[15]);
    }
    __syncthreads();

    // ---- Phases 2+3 per window (KV buffer reused) ----
    #pragma unroll
    for (int w = 0; w < 2; w++) {
        const int rb = w * 64;     // row base in XN for this window
        unsigned qa[2][4];

        // Phase 2: QKV GEMM; Q stays in registers, K/V -> smem
        {
            uint2 qacc[2][2], kvacc[2][4];
            #pragma unroll
            for (int mt = 0; mt < 2; mt++) {
                qacc[mt][0] = make_uint2(0u, 0u); qacc[mt][1] = make_uint2(0u, 0u);
                #pragma unroll
                for (int j = 0; j < 4; j++) kvacc[mt][j] = make_uint2(0u, 0u);
            }
            #pragma unroll
            for (int kt = 0; kt < 4; kt++) {
                unsigned a[2][4];
                #pragma unroll
                for (int mt = 0; mt < 2; mt++)
                    ldsm_x4(saddr(XN + (rb + m0 + mt * 16 + l2) * 72 + kt * 16 + (lane >> 4) * 8),
                            a[mt][0], a[mt][1], a[mt][2], a[mt][3]);
                uint2 qb[2], kvb[4];
                #pragma unroll
                for (int j = 0; j < 2; j++)
                    qb[j] = *(const uint2*)(g_qkvfrag + (((h * 2 + j) * 4 + kt) * 32 + lane) * 2);
                #pragma unroll
                for (int j = 0; j < 4; j++)
                    kvb[j] = *(const uint2*)(g_qkvfrag + (((8 + h * 4 + j) * 4 + kt) * 32 + lane) * 2);
                #pragma unroll
                for (int mt = 0; mt < 2; mt++) {
                    #pragma unroll
                    for (int j = 0; j < 2; j++)
                        mmah(qacc[mt][j], a[mt][0], a[mt][1], a[mt][2], a[mt][3], qb[j].x, qb[j].y);
                    #pragma unroll
                    for (int j = 0; j < 4; j++)
                        mmah(kvacc[mt][j], a[mt][0], a[mt][1], a[mt][2], a[mt][3], kvb[j].x, kvb[j].y);
                }
            }
            unsigned bq0 = g_qkvbh[h * 8 + tig];
            unsigned bq1 = g_qkvbh[h * 8 + 4 + tig];
            #pragma unroll
            for (int mt = 0; mt < 2; mt++) {
                qa[mt][0] = hadd2u(qacc[mt][0].x, bq0);
                qa[mt][1] = hadd2u(qacc[mt][0].y, bq0);
                qa[mt][2] = hadd2u(qacc[mt][1].x, bq1);
                qa[mt][3] = hadd2u(qacc[mt][1].y, bq1);
            }
            #pragma unroll
            for (int j = 0; j < 4; j++) {
                int col = h * 32 + j * 8 + tig * 2;
                unsigned bh = g_qkvbh[32 + h * 16 + j * 4 + tig];
                #pragma unroll
                for (int mt = 0; mt < 2; mt++) {
                    int row = m0 + mt * 16 + g;
                    *(unsigned*)(KV + row * 136 + col)       = hadd2u(kvacc[mt][j].x, bh);
                    *(unsigned*)(KV + (row + 8) * 136 + col) = hadd2u(kvacc[mt][j].y, bh);
                }
            }
        }
        __syncthreads();

        // Phase 3: attention
        {
            unsigned kb[8][2];
            #pragma unroll
            for (int jp = 0; jp < 4; jp++) {
                unsigned r0, r1, r2, r3;
                int j  = (lane >> 4);
                int kh = (lane >> 3) & 1;
                ldsm_x4(saddr(KV + ((jp * 2 + j) * 8 + (lane & 7)) * 136 + h * 16 + kh * 8),
                        r0, r1, r2, r3);
                kb[jp * 2 + 0][0] = r0; kb[jp * 2 + 0][1] = r1;
                kb[jp * 2 + 1][0] = r2; kb[jp * 2 + 1][1] = r3;
            }

            #pragma unroll
            for (int mt = 0; mt < 2; mt++) {
                const uint4* bfp = (const uint4*)(g_biasfh) + (warp * 2 + mt) * 128 + lane;
                uint2 s[8];
                #pragma unroll
                for (int qd = 0; qd < 4; qd++) {
                    uint4 bv = bfp[qd * 32];
                    s[2 * qd].x = bv.x;     s[2 * qd].y = bv.y;
                    s[2 * qd + 1].x = bv.z; s[2 * qd + 1].y = bv.w;
                }
                #pragma unroll
                for (int j = 0; j < 8; j++)
                    mmah(s[j], qa[mt][0], qa[mt][1], qa[mt][2], qa[mt][3], kb[j][0], kb[j][1]);

                #pragma unroll
                for (int j = 0; j < 8; j++) {
                    s[j].x = ex2h2(s[j].x);
                    s[j].y = ex2h2(s[j].y);
                }

                uint2 o[2], o2;
                o[0].x = o[0].y = o[1].x = o[1].y = 0u;
                o2.x = o2.y = 0u;
                #pragma unroll
                for (int kt = 0; kt < 4; kt++) {
                    unsigned v0, v1, v2, v3;
                    ldsm_x4t(saddr(KV + (kt * 16 + (lane & 7) + ((lane >> 3) & 1) * 8) * 136
                                   + 64 + h * 16 + (lane >> 4) * 8),
                             v0, v1, v2, v3);
                    mmah(o[0], s[2 * kt].x, s[2 * kt].y, s[2 * kt + 1].x, s[2 * kt + 1].y, v0, v1);
                    mmah(o[1], s[2 * kt].x, s[2 * kt].y, s[2 * kt + 1].x, s[2 * kt + 1].y, v2, v3);
                    mmah(o2,   s[2 * kt].x, s[2 * kt].y, s[2 * kt + 1].x, s[2 * kt + 1].y,
                         ONESH2, ONESH2);
                }

                float f0 = __fdividef(1.f, hlo2f(o2.x));
                float f1 = __fdividef(1.f, hlo2f(o2.y));
                unsigned i0 = packh2f(f0, f0);
                unsigned i1 = packh2f(f1, f1);
                #pragma unroll
                for (int nt = 0; nt < 2; nt++) {
                    int row = rb + m0 + mt * 16 + g;
                    int col = h * 16 + nt * 8 + tig * 2;
                    *(unsigned*)(XN + row * 72 + col)       = hmul2u(o[nt].x, i0);
                    *(unsigned*)(XN + (row + 8) * 72 + col) = hmul2u(o[nt].y, i1);
                }
            }
        }
        __syncthreads();
    }

    // ---- Phase 4: proj GEMM both windows, stage fp16 results into KV buffer ----
    {
        const int ntb = (warp >> 1) * 2;
        uint2 bf[4][2];
        #pragma unroll
        for (int kt = 0; kt < 4; kt++)
            #pragma unroll
            for (int nt = 0; nt < 2; nt++)
                bf[kt][nt] = *(const uint2*)(g_projfrag + (((ntb + nt) * 4 + kt) * 32 + lane) * 2);

        #pragma unroll
        for (int w = 0; w < 2; w++) {
            const int rb = w * 64;
            uint2 acc[2][2];
            acc[0][0] = make_uint2(0u, 0u); acc[0][1] = make_uint2(0u, 0u);
            acc[1][0] = make_uint2(0u, 0u); acc[1][1] = make_uint2(0u, 0u);
            #pragma unroll
            for (int kt = 0; kt < 4; kt++) {
                unsigned a[2][4];
                #pragma unroll
                for (int mt = 0; mt < 2; mt++)
                    ldsm_x4(saddr(XN + (rb + m0 + mt * 16 + l2) * 72 + kt * 16 + (lane >> 4) * 8),
                            a[mt][0], a[mt][1], a[mt][2], a[mt][3]);
                #pragma unroll
                for (int mt = 0; mt < 2; mt++)
                    #pragma unroll
                    for (int nt = 0; nt < 2; nt++)
                        mmah(acc[mt][nt], a[mt][0], a[mt][1], a[mt][2], a[mt][3],
                             bf[kt][nt].x, bf[kt][nt].y);
            }
            // stage fp16 proj results: KV reused as [128][72]
            #pragma unroll
            for (int mt = 0; mt < 2; mt++)
                #pragma unroll
                for (int nt = 0; nt < 2; nt++) {
                    int row = rb + m0 + mt * 16 + g;
                    int col = (ntb + nt) * 8 + tig * 2;
                    *(unsigned*)(KV + row * 72 + col)       = acc[mt][nt].x;
                    *(unsigned*)(KV + (row + 8) * 72 + col) = acc[mt][nt].y;
                }
        }
    }
    __syncthreads();

    // ---- Epilogue: 64B-coalesced residual read-modify-write ----
    {
        int r    = warp;
        int px16 = lane >> 1;
        int hq   = lane & 1;
        int w    = px16 >> 3;
        int tp   = w * 64 + r * 8 + (px16 & 7);
        const uint4* src = (const uint4*)(KV + tp * 72 + hq * 32);
        uint4 u0 = src[0], u1 = src[1], u2 = src[2], u3 = src[3];
        unsigned hv[16] = {u0.x, u0.y, u0.z, u0.w, u1.x, u1.y, u1.z, u1.w,
                           u2.x, u2.y, u2.z, u2.w, u3.x, u3.y, u3.z, u3.w};
        float ssc = ascale[0];
        int gi = (b * 64 + hq * 32) * 65536 + (wy * 8 + r) * 256 + wpx * 16 + px16;
        #pragma unroll
        for (int i = 0; i < 16; i++) {
            float2 pv = h2f2(hv[i]);
            out[gi]         = x[gi]         + ssc * pv.x;   // channel hq*32 + 2i
            out[gi + 65536] = x[gi + 65536] + ssc * pv.y;   // channel hq*32 + 2i + 1
            gi += 2 * 65536;
        }
    }
}

extern "C" void kernel_launch(void* const* d_in, const int* in_sizes, int n_in,
                              void* d_out, int out_size) {
    const float* x  = (const float*)d_in[0];
    const float* nw = (const float*)d_in[1];
    const float* nb = (const float*)d_in[2];
    const float* qw = (const float*)d_in[3];
    const float* pw = (const float*)d_in[4];
    const float* sc = (const float*)d_in[5];
    const float* rp = (const float*)d_in[6];
    float* out = (float*)d_out;

    cudaFuncSetAttribute(ewa_kernel, cudaFuncAttributeMaxDynamicSharedMemorySize, SMEM_BYTES);

    prep_kernel<<<32, 256>>>(qw, pw, nw, nb, rp);
    ewa_kernel<<<NPAIR, TPB, SMEM_BYTES>>>(x, sc, out);
}